// round 15
// baseline (speedup 1.0000x reference)
#include <cuda_runtime.h>
#include <cuda_bf16.h>
#include <cuda_fp16.h>
#include <cstdint>

#define HW   3136
#define CHW  802816
#define MDIM 100352   // 32*56*56

// ---------------- scratch (no cudaMalloc allowed) ----------------
__device__ float              g_y[(size_t)256 * MDIM];
__device__ unsigned char      g_k[(size_t)256 * MDIM];
__device__ unsigned long long g_csum[256];
__device__ unsigned           g_yminK[256];
__device__ unsigned           g_ymaxK[256];
__device__ int                g_ksum[256];
__device__ float g_mn[256], g_inv[256], g_beta[256];
__device__ __half g_uthih[65536], g_uthil[65536];  // fp16 hi/lo of u^T [j][c]
__device__ __half g_upf16[65536];                  // fp16(u*inv) [i][j]

// ---------------- helpers ----------------
static __device__ __forceinline__ unsigned fkey(float f) {
    unsigned u = __float_as_uint(f);
    return (u & 0x80000000u) ? ~u : (u | 0x80000000u);
}
static __device__ __forceinline__ float kinv(unsigned k) {
    unsigned u = (k & 0x80000000u) ? (k & 0x7fffffffu) : ~k;
    return __uint_as_float(u);
}
static __device__ __forceinline__ void split_f16(float v, __half& hi, __half& lo) {
    hi = __float2half(v);
    lo = __float2half(v - __half2float(hi));
}
static __device__ __forceinline__ void mma_f16(float d[4], const unsigned a[4], const unsigned b[2]) {
    asm volatile(
        "mma.sync.aligned.m16n8k16.row.col.f32.f16.f16.f32 "
        "{%0,%1,%2,%3},{%4,%5,%6,%7},{%8,%9},{%0,%1,%2,%3};"
        : "+f"(d[0]), "+f"(d[1]), "+f"(d[2]), "+f"(d[3])
        : "r"(a[0]), "r"(a[1]), "r"(a[2]), "r"(a[3]), "r"(b[0]), "r"(b[1]));
}
static __device__ __forceinline__ void ldm4(unsigned r[4], uint32_t addr) {
    asm volatile("ldmatrix.sync.aligned.m8n8.x4.shared.b16 {%0,%1,%2,%3}, [%4];"
        : "=r"(r[0]), "=r"(r[1]), "=r"(r[2]), "=r"(r[3]) : "r"(addr));
}
static __device__ __forceinline__ void cp16(uint32_t dst, const void* src) {
    asm volatile("cp.async.cg.shared.global [%0],[%1],16;" :: "r"(dst), "l"(src));
}
static __device__ __forceinline__ unsigned h2u(__half2 h) {
    return *(unsigned*)&h;
}

// -------- pass 0: init accumulators + u^T fp16 hi/lo split --------
__global__ void k_prep0(const float* __restrict__ u) {
    int j = blockIdx.x, c = threadIdx.x;
    if (j == 0) {
        g_csum[c]  = 0ull;
        g_yminK[c] = 0xFFFFFFFFu;
        g_ymaxK[c] = 0u;
        g_ksum[c]  = 0;
    }
    float v = u[c * 256 + j];
    split_f16(v, g_uthih[j * 256 + c], g_uthil[j * 256 + c]);
}

// ==================== GEMM1: y = u^T @ relu(x)  (3-pass fp16 hi/lo, M=128/CTA, 2 CTA/SM) ====================
// buffer: Ah 10240 | Al 10240 | Bh 9216 | Bl 9216 = 38912
#define G1_BUF 38912
__global__ __launch_bounds__(256, 2) void k_gemm1(const float* __restrict__ x) {
    extern __shared__ __align__(16) char smem[];
    int*      sc  = (int*)smem;                  // 256 ints
    unsigned* rmn = (unsigned*)(smem + 1024);    // 128
    unsigned* rmx = (unsigned*)(smem + 1536);    // 128
    char*     bufs = smem + 2048;

    const int tid = threadIdx.x, warp = tid >> 5, lane = tid & 31;
    const int jw = warp & 3, cw = warp >> 2;     // 4 j-warps x 2 px-warps
    const int jb = blockIdx.x;                   // 0/1: j half
    const int cb = blockIdx.y * 128;
    const int c0 = warp * 4;                     // loader: 4 channels per warp
    const int g  = lane;                         // loader: px group of 4

    if (tid < 128) { rmn[tid] = 0xFFFFFFFFu; rmx[tid] = 0u; }
    sc[tid] = 0;
    __syncthreads();

    const int gpx = cb + g * 4;
    const int nb  = gpx / HW;
    const int hwx = gpx - nb * HW;
    const float* xt = x + (size_t)nb * CHW + (size_t)c0 * HW + hwx;

    const uint32_t bufs0 = (uint32_t)__cvta_generic_to_shared(bufs);
    const uint32_t aoff = (uint32_t)((jw * 32 + (lane & 7) + ((lane >> 3) & 1) * 8) * 80
                                     + ((lane >> 4) & 1) * 16);

    float acc[2][8][4];
#pragma unroll
    for (int m = 0; m < 2; ++m)
#pragma unroll
        for (int nf = 0; nf < 8; ++nf)
#pragma unroll
            for (int q = 0; q < 4; ++q) acc[m][nf][q] = 0.f;

    float4 xr[4];

    auto A_issue = [&](int c4, int buf) {
        const int kc = c4 * 32;
        char* base = bufs + buf * G1_BUF;
#pragma unroll
        for (int i = 0; i < 4; ++i) {
            int idx = tid + i * 256;
            int half = idx >> 9, sub = idx & 511;
            int row = sub >> 2, seg = sub & 3;
            const __half* src = (half ? g_uthil : g_uthih) + (jb * 128 + row) * 256 + kc + seg * 8;
            uint32_t dst = (uint32_t)__cvta_generic_to_shared(base + half * 10240 + row * 80 + seg * 16);
            cp16(dst, src);
        }
        asm volatile("cp.async.commit_group;" ::: "memory");
    };
    auto B_sts = [&](int c4, int buf) {
        const int kc = c4 * 32;
        unsigned* Bhw = (unsigned*)(bufs + buf * G1_BUF + 20480);
        unsigned* Blw = (unsigned*)(bufs + buf * G1_BUF + 29696);
        float v[4][4];
#pragma unroll
        for (int cc = 0; cc < 4; ++cc) {
            v[cc][0] = fmaxf(xr[cc].x, 0.f); v[cc][1] = fmaxf(xr[cc].y, 0.f);
            v[cc][2] = fmaxf(xr[cc].z, 0.f); v[cc][3] = fmaxf(xr[cc].w, 0.f);
        }
        if (jb == 0) {
#pragma unroll
            for (int cc = 0; cc < 4; ++cc) {
                int s = (int)llrintf((v[cc][0] + v[cc][1] + v[cc][2] + v[cc][3]) * 65536.f);
                s = __reduce_add_sync(0xffffffffu, s);
                if (lane == 0) atomicAdd(&sc[kc + c0 + cc], s);
            }
        }
        const int w0 = c0 >> 1;                  // word base = warp*2
        const int xo = g & 15;
#pragma unroll
        for (int q = 0; q < 4; ++q) {
            int r = g * 4 + q;
            __half2 h01 = __floats2half2_rn(v[0][q], v[1][q]);
            __half2 h23 = __floats2half2_rn(v[2][q], v[3][q]);
            float2 b01 = __half22float2(h01);
            float2 b23 = __half22float2(h23);
            __half2 l01 = __floats2half2_rn(v[0][q] - b01.x, v[1][q] - b01.y);
            __half2 l23 = __floats2half2_rn(v[2][q] - b23.x, v[3][q] - b23.y);
            Bhw[r * 18 + (w0 ^ xo)]       = h2u(h01);
            Bhw[r * 18 + ((w0 + 1) ^ xo)] = h2u(h23);
            Blw[r * 18 + (w0 ^ xo)]       = h2u(l01);
            Blw[r * 18 + ((w0 + 1) ^ xo)] = h2u(l23);
        }
    };

    A_issue(0, 0);
#pragma unroll
    for (int cc = 0; cc < 4; ++cc) xr[cc] = *(const float4*)(xt + (size_t)cc * HW);
    B_sts(0, 0);

#pragma unroll 2
    for (int c4 = 0; c4 < 8; ++c4) {
        const int buf = c4 & 1;
        asm volatile("cp.async.wait_group 0;" ::: "memory");
        __syncthreads();
        if (c4 < 7) {
            A_issue(c4 + 1, buf ^ 1);
#pragma unroll
            for (int cc = 0; cc < 4; ++cc)
                xr[cc] = *(const float4*)(xt + (size_t)((c4 + 1) * 32 + cc) * HW);
        }
        {
            const uint32_t Ab = bufs0 + buf * G1_BUF + aoff;
            const unsigned* Bhw = (const unsigned*)(bufs + buf * G1_BUF + 20480);
            const unsigned* Blw = (const unsigned*)(bufs + buf * G1_BUF + 29696);
#pragma unroll
            for (int ks = 0; ks < 2; ++ks) {
                unsigned afh[2][4], afl[2][4];
#pragma unroll
                for (int m = 0; m < 2; ++m) {
                    ldm4(afh[m], Ab + m * 1280 + ks * 32);
                    ldm4(afl[m], Ab + 10240u + m * 1280 + ks * 32);
                }
#pragma unroll
                for (int nf = 0; nf < 8; ++nf) {
                    int coln = cw * 64 + nf * 8 + (lane >> 2);
                    int wc   = ks * 8 + (lane & 3);
                    int xo   = (coln >> 2) & 15;
                    int rowb = coln * 18;
                    unsigned bh[2], bl[2];
                    bh[0] = Bhw[rowb + (wc ^ xo)];
                    bh[1] = Bhw[rowb + ((wc + 4) ^ xo)];
                    bl[0] = Blw[rowb + (wc ^ xo)];
                    bl[1] = Blw[rowb + ((wc + 4) ^ xo)];
#pragma unroll
                    for (int m = 0; m < 2; ++m) {
                        mma_f16(acc[m][nf], afh[m], bh);
                        mma_f16(acc[m][nf], afh[m], bl);
                        mma_f16(acc[m][nf], afl[m], bh);
                    }
                }
            }
        }
        if (c4 < 7) B_sts(c4 + 1, buf ^ 1);
    }

    // ---- epilogue: per-row min/max, y store ----
#pragma unroll
    for (int m = 0; m < 2; ++m) {
        float mn0 = 3.4e38f, mx0 = -3.4e38f, mn1 = 3.4e38f, mx1 = -3.4e38f;
#pragma unroll
        for (int nf = 0; nf < 8; ++nf) {
            mn0 = fminf(mn0, fminf(acc[m][nf][0], acc[m][nf][1]));
            mx0 = fmaxf(mx0, fmaxf(acc[m][nf][0], acc[m][nf][1]));
            mn1 = fminf(mn1, fminf(acc[m][nf][2], acc[m][nf][3]));
            mx1 = fmaxf(mx1, fmaxf(acc[m][nf][2], acc[m][nf][3]));
        }
        mn0 = fminf(mn0, __shfl_xor_sync(0xffffffffu, mn0, 1));
        mn0 = fminf(mn0, __shfl_xor_sync(0xffffffffu, mn0, 2));
        mx0 = fmaxf(mx0, __shfl_xor_sync(0xffffffffu, mx0, 1));
        mx0 = fmaxf(mx0, __shfl_xor_sync(0xffffffffu, mx0, 2));
        mn1 = fminf(mn1, __shfl_xor_sync(0xffffffffu, mn1, 1));
        mn1 = fminf(mn1, __shfl_xor_sync(0xffffffffu, mn1, 2));
        mx1 = fmaxf(mx1, __shfl_xor_sync(0xffffffffu, mx1, 1));
        mx1 = fmaxf(mx1, __shfl_xor_sync(0xffffffffu, mx1, 2));
        if ((lane & 3) == 0) {
            int r0 = jw * 32 + m * 16 + (lane >> 2);
            atomicMin(&rmn[r0], fkey(mn0));
            atomicMax(&rmx[r0], fkey(mx0));
            atomicMin(&rmn[r0 + 8], fkey(mn1));
            atomicMax(&rmx[r0 + 8], fkey(mx1));
        }
    }
#pragma unroll
    for (int m = 0; m < 2; ++m) {
        int r0 = jw * 32 + m * 16 + (lane >> 2);
#pragma unroll
        for (int nf = 0; nf < 8; ++nf) {
            int coln = cb + cw * 64 + nf * 8 + (lane & 3) * 2;
            *(float2*)&g_y[(size_t)(jb * 128 + r0) * MDIM + coln] =
                make_float2(acc[m][nf][0], acc[m][nf][1]);
            *(float2*)&g_y[(size_t)(jb * 128 + r0 + 8) * MDIM + coln] =
                make_float2(acc[m][nf][2], acc[m][nf][3]);
        }
    }
    __syncthreads();
    if (tid < 128) {
        atomicMin(&g_yminK[jb * 128 + tid], rmn[tid]);
        atomicMax(&g_ymaxK[jb * 128 + tid], rmx[tid]);
    }
    if (jb == 0) atomicAdd(&g_csum[tid], (unsigned long long)(long long)sc[tid]);
}

// -------- pass 2: quantize (scale computed in-block, identical fp sequence to old prepS) --------
// 100352 = 14 * 7168; block = 7168-elem span in one j row; 256 thr * 28 elems
__global__ __launch_bounds__(256) void k_quant(const float* __restrict__ u,
                                               const float* __restrict__ cl) {
    __shared__ float wred[8];
    __shared__ float sparams[2];   // sc, bias
    int j   = blockIdx.x / 14;
    int seg = blockIdx.x - j * 14;
    int t   = threadIdx.x;

    // issue y loads first (latency hides the reduction below)
    const float4* yb = (const float4*)(g_y + (size_t)j * MDIM + seg * 7168);
    float4 ya[7];
#pragma unroll
    for (int q = 0; q < 7; ++q) ya[q] = __ldcs(yb + q * 256 + t);   // warp: 512B contiguous

    // per-block recompute of mn, s, dmin/scale (same fp order as before)
    float mnc = (float)(((double)g_csum[t] * (1.0 / 65536.0)) / (double)MDIM);
    if (seg == 0 && t == j) g_mn[j] = mnc;
    float p = u[t * 256 + j] * mnc;
#pragma unroll
    for (int off = 16; off > 0; off >>= 1) p += __shfl_down_sync(0xffffffffu, p, off);
    if ((t & 31) == 0) wred[t >> 5] = p;
    __syncthreads();
    if (t == 0) {
        float s = 0.f;
#pragma unroll
        for (int i = 0; i < 8; ++i) s += wred[i];
        float ymin = kinv(g_yminK[j]) - s;
        float ymax = kinv(g_ymaxK[j]) - s;
        float cc = cl[j];
        float dmin = fminf(fmaxf(ymin, -cc), cc);
        float dmax = fminf(fmaxf(ymax, -cc), cc);
        float rng = dmax - dmin;
        float scale = 255.f / ((rng == 0.f) ? 1.f : rng);
        sparams[0] = scale;
        sparams[1] = -(s + dmin) * scale;
        if (seg == 0) g_inv[j] = 1.f / scale;
    }
    __syncthreads();
    const float sc = sparams[0], bias = sparams[1];

    unsigned ob[7];
    int ks = 0;
#pragma unroll
    for (int q = 0; q < 7; ++q) {
        int k0 = (int)fminf(fmaxf(rintf(fmaf(ya[q].x, sc, bias)), 0.f), 255.f);
        int k1 = (int)fminf(fmaxf(rintf(fmaf(ya[q].y, sc, bias)), 0.f), 255.f);
        int k2 = (int)fminf(fmaxf(rintf(fmaf(ya[q].z, sc, bias)), 0.f), 255.f);
        int k3 = (int)fminf(fmaxf(rintf(fmaf(ya[q].w, sc, bias)), 0.f), 255.f);
        ob[q] = (unsigned)k0 | ((unsigned)k1 << 8) | ((unsigned)k2 << 16) | ((unsigned)k3 << 24);
        ks += k0 + k1 + k2 + k3;
    }
    unsigned* kb = (unsigned*)(g_k + (size_t)j * MDIM + seg * 7168);
#pragma unroll
    for (int q = 0; q < 7; ++q) kb[q * 256 + t] = ob[q];            // warp: 128B contiguous
    ks = __reduce_add_sync(0xffffffffu, ks);
    if ((t & 31) == 0) atomicAdd(&g_ksum[j], ks);
}

// -------- pass 3: u' = fp16(u*inv), beta (with -1024*sum(u') for bit-trick B) --------
__global__ void k_prep2(const float* __restrict__ u) {
    __shared__ float red[256], red2[256];
    int i = blockIdx.x, j = threadIdx.x;
    float v = u[i * 256 + j] * g_inv[j];
    __half hv = __float2half(v);
    g_upf16[i * 256 + j] = hv;
    float vq = __half2float(hv);
    float meank = (float)g_ksum[j] / (float)MDIM;
    red[j]  = vq * meank;
    red2[j] = vq;
    __syncthreads();
    for (int sN = 128; sN > 0; sN >>= 1) {
        if (j < sN) { red[j] += red[j + sN]; red2[j] += red2[j + sN]; }
        __syncthreads();
    }
    if (j == 0) g_beta[i] = g_mn[i] - red[0] - 1024.f * red2[0];
}

// ==================== GEMM2: out = u' @ (1024+k) + beta' (fp16, A smem-resident) ====================
// smem: beta 1024 | A 128x264 halves (67584) | B 2x9216
#define G2_A_OFF   1024
#define G2_B_OFF   (1024 + 67584)
#define G2_B_BUF   9216
#define G2_SMEM    (G2_B_OFF + 2 * G2_B_BUF)   // 87040
__global__ __launch_bounds__(256, 2) void k_gemm2(float* __restrict__ out) {
    extern __shared__ __align__(16) char smem[];
    float* sbeta = (float*)smem;
    char*  Abase = smem + G2_A_OFF;
    char*  Bbase = smem + G2_B_OFF;

    const int tid = threadIdx.x, warp = tid >> 5, lane = tid & 31;
    const int jw = warp & 3, cw = warp >> 2;
    const int jb = blockIdx.x;
    const int cb = blockIdx.y * 128;
    const int c0 = warp * 4, g = lane;

    if (tid < 128) sbeta[tid] = g_beta[jb * 128 + tid];

    const unsigned char* kt = g_k + (size_t)c0 * MDIM + cb + g * 4;

    const uint32_t A0 = (uint32_t)__cvta_generic_to_shared(Abase);
    const uint32_t aoff = (uint32_t)((jw * 32 + (lane & 7) + ((lane >> 3) & 1) * 8) * 528
                                     + ((lane >> 4) & 1) * 16);

    float acc[2][8][4];
#pragma unroll
    for (int m = 0; m < 2; ++m)
#pragma unroll
        for (int nf = 0; nf < 8; ++nf)
#pragma unroll
            for (int q = 0; q < 4; ++q) acc[m][nf][q] = 0.f;

    unsigned kr[4];

    // ---- prologue: load ALL of A (u' jb-half, 128 rows x 256 c fp16) into smem ----
#pragma unroll
    for (int i = 0; i < 16; ++i) {
        int idx = tid + i * 256;
        int row = idx >> 5, seg = idx & 31;
        cp16(A0 + row * 528 + seg * 16, g_upf16 + (jb * 128 + row) * 256 + seg * 8);
    }
    asm volatile("cp.async.commit_group;" ::: "memory");

    // fp16(1024 + k) == 0x6400 | k  (exact for k in [0,255]) — pure ALU conversion
    auto B_sts = [&](int buf) {
        unsigned* Bw = (unsigned*)(Bbase + buf * G2_B_BUF);
        const int w0 = c0 >> 1;
        const int xo = g & 15;
#pragma unroll
        for (int cc2 = 0; cc2 < 2; ++cc2) {
            unsigned a = kr[cc2 * 2], b = kr[cc2 * 2 + 1];
#pragma unroll
            for (int q = 0; q < 4; ++q) {
                unsigned t = __byte_perm(a, b, 0x0400 + 0x0101 * q);
                int r = g * 4 + q;
                Bw[r * 18 + ((w0 + cc2) ^ xo)] = (t & 0x00FF00FFu) | 0x64006400u;
            }
        }
    };

#pragma unroll
    for (int cc = 0; cc < 4; ++cc) kr[cc] = *(const unsigned*)(kt + (size_t)cc * MDIM);
    B_sts(0);
    asm volatile("cp.async.wait_group 0;" ::: "memory");
    __syncthreads();

#pragma unroll 2
    for (int c4 = 0; c4 < 8; ++c4) {
        const int buf = c4 & 1;
        if (c4) __syncthreads();
        if (c4 < 7) {
#pragma unroll
            for (int cc = 0; cc < 4; ++cc)
                kr[cc] = *(const unsigned*)(kt + (size_t)((c4 + 1) * 32 + cc) * MDIM);
        }
        {
            const uint32_t Ab = A0 + aoff + c4 * 64;
            const unsigned* Bw = (const unsigned*)(Bbase + buf * G2_B_BUF);
#pragma unroll
            for (int ks = 0; ks < 2; ++ks) {
                unsigned af[2][4];
#pragma unroll
                for (int m = 0; m < 2; ++m)
                    ldm4(af[m], Ab + m * 8448 + ks * 32);
#pragma unroll
                for (int nf = 0; nf < 8; ++nf) {
                    int coln = cw * 64 + nf * 8 + (lane >> 2);
                    int wc   = ks * 8 + (lane & 3);
                    int xo   = (coln >> 2) & 15;
                    int rowb = coln * 18;
                    unsigned b[2];
                    b[0] = Bw[rowb + (wc ^ xo)];
                    b[1] = Bw[rowb + ((wc + 4) ^ xo)];
#pragma unroll
                    for (int m = 0; m < 2; ++m)
                        mma_f16(acc[m][nf], af[m], b);
                }
            }
        }
        if (c4 < 7) B_sts(buf ^ 1);
    }

    // epilogue: add beta', store NCHW
#pragma unroll
    for (int m = 0; m < 2; ++m) {
        int r0 = jw * 32 + m * 16 + (lane >> 2);
        int row0 = jb * 128 + r0;
        float b0 = sbeta[r0], b1 = sbeta[r0 + 8];
#pragma unroll
        for (int nf = 0; nf < 8; ++nf) {
            int col = cb + cw * 64 + nf * 8 + (lane & 3) * 2;
            int n = col / HW, hw2 = col - n * HW;
            *(float2*)&out[(size_t)n * CHW + (size_t)row0 * HW + hw2] =
                make_float2(acc[m][nf][0] + b0, acc[m][nf][1] + b0);
            *(float2*)&out[(size_t)n * CHW + (size_t)(row0 + 8) * HW + hw2] =
                make_float2(acc[m][nf][2] + b1, acc[m][nf][3] + b1);
        }
    }
}

extern "C" void kernel_launch(void* const* d_in, const int* in_sizes, int n_in,
                              void* d_out, int out_size) {
    const float* x  = (const float*)d_in[0];
    const float* u  = (const float*)d_in[1];
    const float* cl = (const float*)d_in[2];
    float* out = (float*)d_out;

    cudaFuncSetAttribute(k_gemm1, cudaFuncAttributeMaxDynamicSharedMemorySize, 2048 + 2 * G1_BUF);
    cudaFuncSetAttribute(k_gemm2, cudaFuncAttributeMaxDynamicSharedMemorySize, G2_SMEM);

    k_prep0<<<256, 256>>>(u);
    k_gemm1<<<dim3(2, 784), 256, 2048 + 2 * G1_BUF>>>(x);
    k_quant<<<3584, 256>>>(u, cl);
    k_prep2<<<256, 256>>>(u);
    k_gemm2<<<dim3(2, 784), 256, G2_SMEM>>>(out);
}

// round 16
// speedup vs baseline: 1.0412x; 1.0412x over previous
#include <cuda_runtime.h>
#include <cuda_bf16.h>
#include <cuda_fp16.h>
#include <cstdint>

#define HW   3136
#define CHW  802816
#define MDIM 100352   // 32*56*56

// ---------------- scratch (no cudaMalloc allowed) ----------------
__device__ float              g_y[(size_t)256 * MDIM];
__device__ unsigned char      g_k[(size_t)256 * MDIM];
__device__ unsigned long long g_csum[256];
__device__ unsigned           g_yminK[256];
__device__ unsigned           g_ymaxK[256];
__device__ int                g_ksum[256];
__device__ float g_mn[256], g_s[256], g_dmin[256], g_scale[256], g_inv[256], g_beta[256];
__device__ __half g_uthih[65536], g_uthil[65536];  // fp16 hi/lo of u^T [j][c]
__device__ __half g_upf16[65536];                  // fp16(u*inv) [i][j]

// ---------------- helpers ----------------
static __device__ __forceinline__ unsigned fkey(float f) {
    unsigned u = __float_as_uint(f);
    return (u & 0x80000000u) ? ~u : (u | 0x80000000u);
}
static __device__ __forceinline__ float kinv(unsigned k) {
    unsigned u = (k & 0x80000000u) ? (k & 0x7fffffffu) : ~k;
    return __uint_as_float(u);
}
static __device__ __forceinline__ void split_f16(float v, __half& hi, __half& lo) {
    hi = __float2half(v);
    lo = __float2half(v - __half2float(hi));
}
static __device__ __forceinline__ void mma_f16(float d[4], const unsigned a[4], const unsigned b[2]) {
    asm volatile(
        "mma.sync.aligned.m16n8k16.row.col.f32.f16.f16.f32 "
        "{%0,%1,%2,%3},{%4,%5,%6,%7},{%8,%9},{%0,%1,%2,%3};"
        : "+f"(d[0]), "+f"(d[1]), "+f"(d[2]), "+f"(d[3])
        : "r"(a[0]), "r"(a[1]), "r"(a[2]), "r"(a[3]), "r"(b[0]), "r"(b[1]));
}
static __device__ __forceinline__ void ldm4(unsigned r[4], uint32_t addr) {
    asm volatile("ldmatrix.sync.aligned.m8n8.x4.shared.b16 {%0,%1,%2,%3}, [%4];"
        : "=r"(r[0]), "=r"(r[1]), "=r"(r[2]), "=r"(r[3]) : "r"(addr));
}
static __device__ __forceinline__ void cp16(uint32_t dst, const void* src) {
    asm volatile("cp.async.cg.shared.global [%0],[%1],16;" :: "r"(dst), "l"(src));
}
static __device__ __forceinline__ unsigned h2u(__half2 h) {
    return *(unsigned*)&h;
}

// -------- pass 0: init accumulators + u^T fp16 hi/lo split --------
__global__ void k_prep0(const float* __restrict__ u) {
    int j = blockIdx.x, c = threadIdx.x;
    if (j == 0) {
        g_csum[c]  = 0ull;
        g_yminK[c] = 0xFFFFFFFFu;
        g_ymaxK[c] = 0u;
        g_ksum[c]  = 0;
    }
    float v = u[c * 256 + j];
    split_f16(v, g_uthih[j * 256 + c], g_uthil[j * 256 + c]);
}

// ==================== GEMM1: y = u^T @ relu(x)  (3-pass fp16 hi/lo, M=128/CTA, 2 CTA/SM) ====================
// buffer: Ah 10240 | Al 10240 | Bh 9216 | Bl 9216 = 38912
#define G1_BUF 38912
__global__ __launch_bounds__(256, 2) void k_gemm1(const float* __restrict__ x) {
    extern __shared__ __align__(16) char smem[];
    int*      sc  = (int*)smem;                  // 256 ints
    unsigned* rmn = (unsigned*)(smem + 1024);    // 128
    unsigned* rmx = (unsigned*)(smem + 1536);    // 128
    char*     bufs = smem + 2048;

    const int tid = threadIdx.x, warp = tid >> 5, lane = tid & 31;
    const int jw = warp & 3, cw = warp >> 2;     // 4 j-warps x 2 px-warps
    const int jb = blockIdx.x;                   // 0/1: j half
    const int cb = blockIdx.y * 128;
    const int c0 = warp * 4;                     // loader: 4 channels per warp
    const int g  = lane;                         // loader: px group of 4

    if (tid < 128) { rmn[tid] = 0xFFFFFFFFu; rmx[tid] = 0u; }
    sc[tid] = 0;
    __syncthreads();

    const int gpx = cb + g * 4;
    const int nb  = gpx / HW;
    const int hwx = gpx - nb * HW;
    const float* xt = x + (size_t)nb * CHW + (size_t)c0 * HW + hwx;

    const uint32_t bufs0 = (uint32_t)__cvta_generic_to_shared(bufs);
    const uint32_t aoff = (uint32_t)((jw * 32 + (lane & 7) + ((lane >> 3) & 1) * 8) * 80
                                     + ((lane >> 4) & 1) * 16);

    float acc[2][8][4];
#pragma unroll
    for (int m = 0; m < 2; ++m)
#pragma unroll
        for (int nf = 0; nf < 8; ++nf)
#pragma unroll
            for (int q = 0; q < 4; ++q) acc[m][nf][q] = 0.f;

    float4 xr[4];

    auto A_issue = [&](int c4, int buf) {
        const int kc = c4 * 32;
        char* base = bufs + buf * G1_BUF;
#pragma unroll
        for (int i = 0; i < 4; ++i) {
            int idx = tid + i * 256;
            int half = idx >> 9, sub = idx & 511;
            int row = sub >> 2, seg = sub & 3;
            const __half* src = (half ? g_uthil : g_uthih) + (jb * 128 + row) * 256 + kc + seg * 8;
            uint32_t dst = (uint32_t)__cvta_generic_to_shared(base + half * 10240 + row * 80 + seg * 16);
            cp16(dst, src);
        }
        asm volatile("cp.async.commit_group;" ::: "memory");
    };
    auto B_sts = [&](int c4, int buf) {
        const int kc = c4 * 32;
        unsigned* Bhw = (unsigned*)(bufs + buf * G1_BUF + 20480);
        unsigned* Blw = (unsigned*)(bufs + buf * G1_BUF + 29696);
        float v[4][4];
#pragma unroll
        for (int cc = 0; cc < 4; ++cc) {
            v[cc][0] = fmaxf(xr[cc].x, 0.f); v[cc][1] = fmaxf(xr[cc].y, 0.f);
            v[cc][2] = fmaxf(xr[cc].z, 0.f); v[cc][3] = fmaxf(xr[cc].w, 0.f);
        }
        if (jb == 0) {
#pragma unroll
            for (int cc = 0; cc < 4; ++cc) {
                int s = (int)llrintf((v[cc][0] + v[cc][1] + v[cc][2] + v[cc][3]) * 65536.f);
                s = __reduce_add_sync(0xffffffffu, s);
                if (lane == 0) atomicAdd(&sc[kc + c0 + cc], s);
            }
        }
        const int w0 = c0 >> 1;                  // word base = warp*2
        const int xo = g & 15;
#pragma unroll
        for (int q = 0; q < 4; ++q) {
            int r = g * 4 + q;
            __half2 h01 = __floats2half2_rn(v[0][q], v[1][q]);
            __half2 h23 = __floats2half2_rn(v[2][q], v[3][q]);
            float2 b01 = __half22float2(h01);
            float2 b23 = __half22float2(h23);
            __half2 l01 = __floats2half2_rn(v[0][q] - b01.x, v[1][q] - b01.y);
            __half2 l23 = __floats2half2_rn(v[2][q] - b23.x, v[3][q] - b23.y);
            Bhw[r * 18 + (w0 ^ xo)]       = h2u(h01);
            Bhw[r * 18 + ((w0 + 1) ^ xo)] = h2u(h23);
            Blw[r * 18 + (w0 ^ xo)]       = h2u(l01);
            Blw[r * 18 + ((w0 + 1) ^ xo)] = h2u(l23);
        }
    };

    A_issue(0, 0);
#pragma unroll
    for (int cc = 0; cc < 4; ++cc) xr[cc] = *(const float4*)(xt + (size_t)cc * HW);
    B_sts(0, 0);

#pragma unroll 2
    for (int c4 = 0; c4 < 8; ++c4) {
        const int buf = c4 & 1;
        asm volatile("cp.async.wait_group 0;" ::: "memory");
        __syncthreads();
        if (c4 < 7) {
            A_issue(c4 + 1, buf ^ 1);
#pragma unroll
            for (int cc = 0; cc < 4; ++cc)
                xr[cc] = *(const float4*)(xt + (size_t)((c4 + 1) * 32 + cc) * HW);
        }
        {
            const uint32_t Ab = bufs0 + buf * G1_BUF + aoff;
            const unsigned* Bhw = (const unsigned*)(bufs + buf * G1_BUF + 20480);
            const unsigned* Blw = (const unsigned*)(bufs + buf * G1_BUF + 29696);
#pragma unroll
            for (int ks = 0; ks < 2; ++ks) {
                unsigned afh[2][4], afl[2][4];
#pragma unroll
                for (int m = 0; m < 2; ++m) {
                    ldm4(afh[m], Ab + m * 1280 + ks * 32);
                    ldm4(afl[m], Ab + 10240u + m * 1280 + ks * 32);
                }
#pragma unroll
                for (int nf = 0; nf < 8; ++nf) {
                    int coln = cw * 64 + nf * 8 + (lane >> 2);
                    int wc   = ks * 8 + (lane & 3);
                    int xo   = (coln >> 2) & 15;
                    int rowb = coln * 18;
                    unsigned bh[2], bl[2];
                    bh[0] = Bhw[rowb + (wc ^ xo)];
                    bh[1] = Bhw[rowb + ((wc + 4) ^ xo)];
                    bl[0] = Blw[rowb + (wc ^ xo)];
                    bl[1] = Blw[rowb + ((wc + 4) ^ xo)];
#pragma unroll
                    for (int m = 0; m < 2; ++m) {
                        mma_f16(acc[m][nf], afh[m], bh);
                        mma_f16(acc[m][nf], afh[m], bl);
                        mma_f16(acc[m][nf], afl[m], bh);
                    }
                }
            }
        }
        if (c4 < 7) B_sts(c4 + 1, buf ^ 1);
    }

    // ---- epilogue: per-row min/max, y store ----
#pragma unroll
    for (int m = 0; m < 2; ++m) {
        float mn0 = 3.4e38f, mx0 = -3.4e38f, mn1 = 3.4e38f, mx1 = -3.4e38f;
#pragma unroll
        for (int nf = 0; nf < 8; ++nf) {
            mn0 = fminf(mn0, fminf(acc[m][nf][0], acc[m][nf][1]));
            mx0 = fmaxf(mx0, fmaxf(acc[m][nf][0], acc[m][nf][1]));
            mn1 = fminf(mn1, fminf(acc[m][nf][2], acc[m][nf][3]));
            mx1 = fmaxf(mx1, fmaxf(acc[m][nf][2], acc[m][nf][3]));
        }
        mn0 = fminf(mn0, __shfl_xor_sync(0xffffffffu, mn0, 1));
        mn0 = fminf(mn0, __shfl_xor_sync(0xffffffffu, mn0, 2));
        mx0 = fmaxf(mx0, __shfl_xor_sync(0xffffffffu, mx0, 1));
        mx0 = fmaxf(mx0, __shfl_xor_sync(0xffffffffu, mx0, 2));
        mn1 = fminf(mn1, __shfl_xor_sync(0xffffffffu, mn1, 1));
        mn1 = fminf(mn1, __shfl_xor_sync(0xffffffffu, mn1, 2));
        mx1 = fmaxf(mx1, __shfl_xor_sync(0xffffffffu, mx1, 1));
        mx1 = fmaxf(mx1, __shfl_xor_sync(0xffffffffu, mx1, 2));
        if ((lane & 3) == 0) {
            int r0 = jw * 32 + m * 16 + (lane >> 2);
            atomicMin(&rmn[r0], fkey(mn0));
            atomicMax(&rmx[r0], fkey(mx0));
            atomicMin(&rmn[r0 + 8], fkey(mn1));
            atomicMax(&rmx[r0 + 8], fkey(mx1));
        }
    }
#pragma unroll
    for (int m = 0; m < 2; ++m) {
        int r0 = jw * 32 + m * 16 + (lane >> 2);
#pragma unroll
        for (int nf = 0; nf < 8; ++nf) {
            int coln = cb + cw * 64 + nf * 8 + (lane & 3) * 2;
            *(float2*)&g_y[(size_t)(jb * 128 + r0) * MDIM + coln] =
                make_float2(acc[m][nf][0], acc[m][nf][1]);
            *(float2*)&g_y[(size_t)(jb * 128 + r0 + 8) * MDIM + coln] =
                make_float2(acc[m][nf][2], acc[m][nf][3]);
        }
    }
    __syncthreads();
    if (tid < 128) {
        atomicMin(&g_yminK[jb * 128 + tid], rmn[tid]);
        atomicMax(&g_ymaxK[jb * 128 + tid], rmx[tid]);
    }
    if (jb == 0) atomicAdd(&g_csum[tid], (unsigned long long)(long long)sc[tid]);
}

// -------- pass 2: mn, s[j] (exact fp32 from u), dmin/scale/inv --------
__global__ void k_prepS(const float* __restrict__ u, const float* __restrict__ cl) {
    __shared__ float wred[8];
    int j = blockIdx.x, c = threadIdx.x;
    int lane = c & 31, warp = c >> 5;
    float mnc = (float)(((double)g_csum[c] * (1.0 / 65536.0)) / (double)MDIM);
    if (c == j) g_mn[j] = mnc;
    float p = u[c * 256 + j] * mnc;
#pragma unroll
    for (int off = 16; off > 0; off >>= 1) p += __shfl_down_sync(0xffffffffu, p, off);
    if (lane == 0) wred[warp] = p;
    __syncthreads();
    if (c == 0) {
        float s = 0.f;
#pragma unroll
        for (int i = 0; i < 8; ++i) s += wred[i];
        g_s[j] = s;
        float ymin = kinv(g_yminK[j]) - s;
        float ymax = kinv(g_ymaxK[j]) - s;
        float cc = cl[j];
        float dmin = fminf(fmaxf(ymin, -cc), cc);
        float dmax = fminf(fmaxf(ymax, -cc), cc);
        float rng = dmax - dmin;
        float scale = 255.f / ((rng == 0.f) ? 1.f : rng);
        g_dmin[j]  = dmin;
        g_scale[j] = scale;
        g_inv[j]   = 1.f / scale;
    }
}

// -------- pass 3: quantize, fully-coalesced: block = 7168-elem span in one j row --------
// 100352 = 14 * 7168; 7168 = 256 threads * 28 elems (7 float4, stride 1024 elems)
__global__ __launch_bounds__(256) void k_quant() {
    int j   = blockIdx.x / 14;
    int seg = blockIdx.x - j * 14;
    int t   = threadIdx.x;
    float sc = g_scale[j];
    float bias = -(g_s[j] + g_dmin[j]) * sc;
    const float4* yb = (const float4*)(g_y + (size_t)j * MDIM + seg * 7168);
    float4 ya[7];
#pragma unroll
    for (int q = 0; q < 7; ++q) ya[q] = __ldcs(yb + q * 256 + t);   // warp: 512B contiguous
    unsigned ob[7];
    int ks = 0;
#pragma unroll
    for (int q = 0; q < 7; ++q) {
        int k0 = (int)fminf(fmaxf(rintf(fmaf(ya[q].x, sc, bias)), 0.f), 255.f);
        int k1 = (int)fminf(fmaxf(rintf(fmaf(ya[q].y, sc, bias)), 0.f), 255.f);
        int k2 = (int)fminf(fmaxf(rintf(fmaf(ya[q].z, sc, bias)), 0.f), 255.f);
        int k3 = (int)fminf(fmaxf(rintf(fmaf(ya[q].w, sc, bias)), 0.f), 255.f);
        ob[q] = (unsigned)k0 | ((unsigned)k1 << 8) | ((unsigned)k2 << 16) | ((unsigned)k3 << 24);
        ks += k0 + k1 + k2 + k3;
    }
    unsigned* kb = (unsigned*)(g_k + (size_t)j * MDIM + seg * 7168);
#pragma unroll
    for (int q = 0; q < 7; ++q) kb[q * 256 + t] = ob[q];            // warp: 128B contiguous
    ks = __reduce_add_sync(0xffffffffu, ks);
    if ((t & 31) == 0) atomicAdd(&g_ksum[j], ks);
}

// -------- pass 4: u' = fp16(u*inv), beta — warp-shuffle reduction (2 barriers) --------
__global__ void k_prep2(const float* __restrict__ u) {
    __shared__ float w1[8], w2[8];
    int i = blockIdx.x, j = threadIdx.x;
    int lane = j & 31, warp = j >> 5;
    float v = u[i * 256 + j] * g_inv[j];
    __half hv = __float2half(v);
    g_upf16[i * 256 + j] = hv;
    float vq = __half2float(hv);
    float meank = (float)g_ksum[j] / (float)MDIM;
    float r1 = vq * meank;
    float r2 = vq;
#pragma unroll
    for (int off = 16; off > 0; off >>= 1) {
        r1 += __shfl_down_sync(0xffffffffu, r1, off);
        r2 += __shfl_down_sync(0xffffffffu, r2, off);
    }
    if (lane == 0) { w1[warp] = r1; w2[warp] = r2; }
    __syncthreads();
    if (j == 0) {
        float s1 = 0.f, s2 = 0.f;
#pragma unroll
        for (int q = 0; q < 8; ++q) { s1 += w1[q]; s2 += w2[q]; }
        g_beta[i] = g_mn[i] - s1 - 1024.f * s2;
    }
}

// ==================== GEMM2: out = u' @ (1024+k) + beta' (fp16, M=128/CTA, 2 CTA/SM) ====================
// buffer: A 10240 | B 9216 = 19456
#define G2_BUF 19456
__global__ __launch_bounds__(256, 2) void k_gemm2(float* __restrict__ out) {
    extern __shared__ __align__(16) char smem[];
    float* sbeta = (float*)smem;                 // 128 floats (pad to 1024)
    char*  bufs  = smem + 1024;

    const int tid = threadIdx.x, warp = tid >> 5, lane = tid & 31;
    const int jw = warp & 3, cw = warp >> 2;
    const int jb = blockIdx.x;
    const int cb = blockIdx.y * 128;
    const int c0 = warp * 4, g = lane;

    if (tid < 128) sbeta[tid] = g_beta[jb * 128 + tid];
    __syncthreads();

    const unsigned char* kt = g_k + (size_t)c0 * MDIM + cb + g * 4;

    const uint32_t bufs0 = (uint32_t)__cvta_generic_to_shared(bufs);
    const uint32_t aoff = (uint32_t)((jw * 32 + (lane & 7) + ((lane >> 3) & 1) * 8) * 80
                                     + ((lane >> 4) & 1) * 16);

    float acc[2][8][4];
#pragma unroll
    for (int m = 0; m < 2; ++m)
#pragma unroll
        for (int nf = 0; nf < 8; ++nf)
#pragma unroll
            for (int q = 0; q < 4; ++q) acc[m][nf][q] = 0.f;

    unsigned kr[4];

    auto A_issue = [&](int c4, int buf) {
        const int kc = c4 * 32;
        char* base = bufs + buf * G2_BUF;
#pragma unroll
        for (int i = 0; i < 2; ++i) {
            int idx = tid + i * 256;
            int row = idx >> 2, seg = idx & 3;
            const __half* src = g_upf16 + (jb * 128 + row) * 256 + kc + seg * 8;
            uint32_t dst = (uint32_t)__cvta_generic_to_shared(base + row * 80 + seg * 16);
            cp16(dst, src);
        }
        asm volatile("cp.async.commit_group;" ::: "memory");
    };
    // fp16(1024 + k) == 0x6400 | k  (exact for k in [0,255]) — pure ALU conversion
    auto B_sts = [&](int buf) {
        unsigned* Bw = (unsigned*)(bufs + buf * G2_BUF + 10240);
        const int w0 = c0 >> 1;
        const int xo = g & 15;
#pragma unroll
        for (int cc2 = 0; cc2 < 2; ++cc2) {
            unsigned a = kr[cc2 * 2], b = kr[cc2 * 2 + 1];
#pragma unroll
            for (int q = 0; q < 4; ++q) {
                unsigned t = __byte_perm(a, b, 0x0400 + 0x0101 * q);
                int r = g * 4 + q;
                Bw[r * 18 + ((w0 + cc2) ^ xo)] = (t & 0x00FF00FFu) | 0x64006400u;
            }
        }
    };

    A_issue(0, 0);
#pragma unroll
    for (int cc = 0; cc < 4; ++cc) kr[cc] = *(const unsigned*)(kt + (size_t)cc * MDIM);
    B_sts(0);

#pragma unroll 2
    for (int c4 = 0; c4 < 8; ++c4) {
        const int buf = c4 & 1;
        asm volatile("cp.async.wait_group 0;" ::: "memory");
        __syncthreads();
        if (c4 < 7) {
            A_issue(c4 + 1, buf ^ 1);
#pragma unroll
            for (int cc = 0; cc < 4; ++cc)
                kr[cc] = *(const unsigned*)(kt + (size_t)((c4 + 1) * 32 + cc) * MDIM);
        }
        {
            const uint32_t Ab = bufs0 + buf * G2_BUF + aoff;
            const unsigned* Bw = (const unsigned*)(bufs + buf * G2_BUF + 10240);
#pragma unroll
            for (int ks = 0; ks < 2; ++ks) {
                unsigned af[2][4];
#pragma unroll
                for (int m = 0; m < 2; ++m)
                    ldm4(af[m], Ab + m * 1280 + ks * 32);
#pragma unroll
                for (int nf = 0; nf < 8; ++nf) {
                    int coln = cw * 64 + nf * 8 + (lane >> 2);
                    int wc   = ks * 8 + (lane & 3);
                    int xo   = (coln >> 2) & 15;
                    int rowb = coln * 18;
                    unsigned b[2];
                    b[0] = Bw[rowb + (wc ^ xo)];
                    b[1] = Bw[rowb + ((wc + 4) ^ xo)];
#pragma unroll
                    for (int m = 0; m < 2; ++m)
                        mma_f16(acc[m][nf], af[m], b);
                }
            }
        }
        if (c4 < 7) B_sts(buf ^ 1);
    }

    // epilogue: add beta', store NCHW
#pragma unroll
    for (int m = 0; m < 2; ++m) {
        int r0 = jw * 32 + m * 16 + (lane >> 2);
        int row0 = jb * 128 + r0;
        float b0 = sbeta[r0], b1 = sbeta[r0 + 8];
#pragma unroll
        for (int nf = 0; nf < 8; ++nf) {
            int col = cb + cw * 64 + nf * 8 + (lane & 3) * 2;
            int n = col / HW, hw2 = col - n * HW;
            *(float2*)&out[(size_t)n * CHW + (size_t)row0 * HW + hw2] =
                make_float2(acc[m][nf][0] + b0, acc[m][nf][1] + b0);
            *(float2*)&out[(size_t)n * CHW + (size_t)(row0 + 8) * HW + hw2] =
                make_float2(acc[m][nf][2] + b1, acc[m][nf][3] + b1);
        }
    }
}

extern "C" void kernel_launch(void* const* d_in, const int* in_sizes, int n_in,
                              void* d_out, int out_size) {
    const float* x  = (const float*)d_in[0];
    const float* u  = (const float*)d_in[1];
    const float* cl = (const float*)d_in[2];
    float* out = (float*)d_out;

    cudaFuncSetAttribute(k_gemm1, cudaFuncAttributeMaxDynamicSharedMemorySize, 2048 + 2 * G1_BUF);
    cudaFuncSetAttribute(k_gemm2, cudaFuncAttributeMaxDynamicSharedMemorySize, 1024 + 2 * G2_BUF);

    k_prep0<<<256, 256>>>(u);
    k_gemm1<<<dim3(2, 784), 256, 2048 + 2 * G1_BUF>>>(x);
    k_prepS<<<256, 256>>>(u, cl);
    k_quant<<<3584, 256>>>();
    k_prep2<<<256, 256>>>(u);
    k_gemm2<<<dim3(2, 784), 256, 1024 + 2 * G2_BUF>>>(out);
}

// round 17
// speedup vs baseline: 1.0953x; 1.0519x over previous
#include <cuda_runtime.h>
#include <cuda_bf16.h>
#include <cuda_fp16.h>
#include <cstdint>

#define HW   3136
#define CHW  802816
#define MDIM 100352   // 32*56*56

// ---------------- scratch (no cudaMalloc allowed) ----------------
__device__ float              g_y[(size_t)256 * MDIM];
__device__ unsigned char      g_k[(size_t)256 * MDIM];
__device__ unsigned long long g_csum[256];
__device__ unsigned           g_yminK[256];
__device__ unsigned           g_ymaxK[256];
__device__ int                g_ksum[256];
__device__ float g_mn[256], g_s[256], g_dmin[256], g_scale[256], g_inv[256], g_beta[256];
__device__ __half g_uthih[65536], g_uthil[65536];  // fp16 hi/lo of u^T [j][c]
__device__ __half g_upf16[65536];                  // fp16(u*inv) [i][j]

// ---------------- helpers ----------------
static __device__ __forceinline__ unsigned fkey(float f) {
    unsigned u = __float_as_uint(f);
    return (u & 0x80000000u) ? ~u : (u | 0x80000000u);
}
static __device__ __forceinline__ float kinv(unsigned k) {
    unsigned u = (k & 0x80000000u) ? (k & 0x7fffffffu) : ~k;
    return __uint_as_float(u);
}
static __device__ __forceinline__ void split_f16(float v, __half& hi, __half& lo) {
    hi = __float2half(v);
    lo = __float2half(v - __half2float(hi));
}
static __device__ __forceinline__ void mma_f16(float d[4], const unsigned a[4], const unsigned b[2]) {
    asm volatile(
        "mma.sync.aligned.m16n8k16.row.col.f32.f16.f16.f32 "
        "{%0,%1,%2,%3},{%4,%5,%6,%7},{%8,%9},{%0,%1,%2,%3};"
        : "+f"(d[0]), "+f"(d[1]), "+f"(d[2]), "+f"(d[3])
        : "r"(a[0]), "r"(a[1]), "r"(a[2]), "r"(a[3]), "r"(b[0]), "r"(b[1]));
}
static __device__ __forceinline__ void ldm4(unsigned r[4], uint32_t addr) {
    asm volatile("ldmatrix.sync.aligned.m8n8.x4.shared.b16 {%0,%1,%2,%3}, [%4];"
        : "=r"(r[0]), "=r"(r[1]), "=r"(r[2]), "=r"(r[3]) : "r"(addr));
}
static __device__ __forceinline__ void cp16(uint32_t dst, const void* src) {
    asm volatile("cp.async.cg.shared.global [%0],[%1],16;" :: "r"(dst), "l"(src));
}
static __device__ __forceinline__ unsigned h2u(__half2 h) {
    return *(unsigned*)&h;
}

// -------- pass 0: init accumulators + u^T fp16 hi/lo split --------
__global__ void k_prep0(const float* __restrict__ u) {
    int j = blockIdx.x, c = threadIdx.x;
    if (j == 0) {
        g_csum[c]  = 0ull;
        g_yminK[c] = 0xFFFFFFFFu;
        g_ymaxK[c] = 0u;
        g_ksum[c]  = 0;
    }
    float v = u[c * 256 + j];
    split_f16(v, g_uthih[j * 256 + c], g_uthil[j * 256 + c]);
}

// ==================== GEMM1: y = u^T @ relu(x)  (3-pass fp16, M=128/CTA, N=112 px, 2 CTA/SM) ====================
// buffer: Ah 10240 | Al 10240 | Bh 8064 | Bl 8064 = 36608
#define G1_BUF 36608
__global__ __launch_bounds__(256, 2) void k_gemm1(const float* __restrict__ x) {
    extern __shared__ __align__(16) char smem[];
    int*      sc  = (int*)smem;                  // 256 ints
    unsigned* rmn = (unsigned*)(smem + 1024);    // 128
    unsigned* rmx = (unsigned*)(smem + 1536);    // 128
    char*     bufs = smem + 2048;

    const int tid = threadIdx.x, warp = tid >> 5, lane = tid & 31;
    const int jw = warp & 3, cw = warp >> 2;     // 4 j-warps x 2 px-warps
    const int jb = blockIdx.x;                   // 0/1: j half
    const int cb = blockIdx.y * 112;
    const int c0 = warp * 4;                     // loader: 4 channels per warp
    const int g  = lane;                         // loader: px group of 4
    const bool act = g < 28;                     // 112 px = 28 groups

    if (tid < 128) { rmn[tid] = 0xFFFFFFFFu; rmx[tid] = 0u; }
    sc[tid] = 0;
    __syncthreads();

    const int gpx = cb + g * 4;
    const int gpc = act ? gpx : 0;
    const int nb  = gpc / HW;
    const int hwx = gpc - nb * HW;
    const float* xt = x + (size_t)nb * CHW + (size_t)c0 * HW + hwx;

    const uint32_t bufs0 = (uint32_t)__cvta_generic_to_shared(bufs);
    const uint32_t aoff = (uint32_t)((jw * 32 + (lane & 7) + ((lane >> 3) & 1) * 8) * 80
                                     + ((lane >> 4) & 1) * 16);

    float acc[2][7][4];
#pragma unroll
    for (int m = 0; m < 2; ++m)
#pragma unroll
        for (int nf = 0; nf < 7; ++nf)
#pragma unroll
            for (int q = 0; q < 4; ++q) acc[m][nf][q] = 0.f;

    float4 xr[4] = {};

    auto A_issue = [&](int c4, int buf) {
        const int kc = c4 * 32;
        char* base = bufs + buf * G1_BUF;
#pragma unroll
        for (int i = 0; i < 4; ++i) {
            int idx = tid + i * 256;
            int half = idx >> 9, sub = idx & 511;
            int row = sub >> 2, seg = sub & 3;
            const __half* src = (half ? g_uthil : g_uthih) + (jb * 128 + row) * 256 + kc + seg * 8;
            uint32_t dst = (uint32_t)__cvta_generic_to_shared(base + half * 10240 + row * 80 + seg * 16);
            cp16(dst, src);
        }
        asm volatile("cp.async.commit_group;" ::: "memory");
    };
    auto X_load = [&](int c4) {
        if (act) {
#pragma unroll
            for (int cc = 0; cc < 4; ++cc)
                xr[cc] = *(const float4*)(xt + (size_t)(c4 * 32 + cc) * HW);
        }
    };
    auto B_sts = [&](int c4, int buf) {
        const int kc = c4 * 32;
        unsigned* Bhw = (unsigned*)(bufs + buf * G1_BUF + 20480);
        unsigned* Blw = (unsigned*)(bufs + buf * G1_BUF + 28544);
        float v[4][4];
#pragma unroll
        for (int cc = 0; cc < 4; ++cc) {
            v[cc][0] = fmaxf(xr[cc].x, 0.f); v[cc][1] = fmaxf(xr[cc].y, 0.f);
            v[cc][2] = fmaxf(xr[cc].z, 0.f); v[cc][3] = fmaxf(xr[cc].w, 0.f);
        }
        if (jb == 0) {
#pragma unroll
            for (int cc = 0; cc < 4; ++cc) {
                int s = (int)llrintf((v[cc][0] + v[cc][1] + v[cc][2] + v[cc][3]) * 65536.f);
                s = __reduce_add_sync(0xffffffffu, s);
                if (lane == 0) atomicAdd(&sc[kc + c0 + cc], s);
            }
        }
        if (act) {
            const int w0 = c0 >> 1;              // word base = warp*2
            const int xo = g & 15;
#pragma unroll
            for (int q = 0; q < 4; ++q) {
                int r = g * 4 + q;
                __half2 h01 = __floats2half2_rn(v[0][q], v[1][q]);
                __half2 h23 = __floats2half2_rn(v[2][q], v[3][q]);
                float2 b01 = __half22float2(h01);
                float2 b23 = __half22float2(h23);
                __half2 l01 = __floats2half2_rn(v[0][q] - b01.x, v[1][q] - b01.y);
                __half2 l23 = __floats2half2_rn(v[2][q] - b23.x, v[3][q] - b23.y);
                Bhw[r * 18 + (w0 ^ xo)]       = h2u(h01);
                Bhw[r * 18 + ((w0 + 1) ^ xo)] = h2u(h23);
                Blw[r * 18 + (w0 ^ xo)]       = h2u(l01);
                Blw[r * 18 + ((w0 + 1) ^ xo)] = h2u(l23);
            }
        }
    };

    A_issue(0, 0);
    X_load(0);
    B_sts(0, 0);

#pragma unroll 2
    for (int c4 = 0; c4 < 8; ++c4) {
        const int buf = c4 & 1;
        asm volatile("cp.async.wait_group 0;" ::: "memory");
        __syncthreads();
        if (c4 < 7) {
            A_issue(c4 + 1, buf ^ 1);
            X_load(c4 + 1);
        }
        {
            const uint32_t Ab = bufs0 + buf * G1_BUF + aoff;
            const unsigned* Bhw = (const unsigned*)(bufs + buf * G1_BUF + 20480);
            const unsigned* Blw = (const unsigned*)(bufs + buf * G1_BUF + 28544);
#pragma unroll
            for (int ks = 0; ks < 2; ++ks) {
                unsigned afh[2][4], afl[2][4];
#pragma unroll
                for (int m = 0; m < 2; ++m) {
                    ldm4(afh[m], Ab + m * 1280 + ks * 32);
                    ldm4(afl[m], Ab + 10240u + m * 1280 + ks * 32);
                }
#pragma unroll
                for (int nf = 0; nf < 7; ++nf) {
                    int coln = cw * 56 + nf * 8 + (lane >> 2);
                    int wc   = ks * 8 + (lane & 3);
                    int xo   = (coln >> 2) & 15;
                    int rowb = coln * 18;
                    unsigned bh[2], bl[2];
                    bh[0] = Bhw[rowb + (wc ^ xo)];
                    bh[1] = Bhw[rowb + ((wc + 4) ^ xo)];
                    bl[0] = Blw[rowb + (wc ^ xo)];
                    bl[1] = Blw[rowb + ((wc + 4) ^ xo)];
#pragma unroll
                    for (int m = 0; m < 2; ++m) {
                        mma_f16(acc[m][nf], afh[m], bh);
                        mma_f16(acc[m][nf], afh[m], bl);
                        mma_f16(acc[m][nf], afl[m], bh);
                    }
                }
            }
        }
        if (c4 < 7) B_sts(c4 + 1, buf ^ 1);
    }

    // ---- epilogue: per-row min/max, y store ----
#pragma unroll
    for (int m = 0; m < 2; ++m) {
        float mn0 = 3.4e38f, mx0 = -3.4e38f, mn1 = 3.4e38f, mx1 = -3.4e38f;
#pragma unroll
        for (int nf = 0; nf < 7; ++nf) {
            mn0 = fminf(mn0, fminf(acc[m][nf][0], acc[m][nf][1]));
            mx0 = fmaxf(mx0, fmaxf(acc[m][nf][0], acc[m][nf][1]));
            mn1 = fminf(mn1, fminf(acc[m][nf][2], acc[m][nf][3]));
            mx1 = fmaxf(mx1, fmaxf(acc[m][nf][2], acc[m][nf][3]));
        }
        mn0 = fminf(mn0, __shfl_xor_sync(0xffffffffu, mn0, 1));
        mn0 = fminf(mn0, __shfl_xor_sync(0xffffffffu, mn0, 2));
        mx0 = fmaxf(mx0, __shfl_xor_sync(0xffffffffu, mx0, 1));
        mx0 = fmaxf(mx0, __shfl_xor_sync(0xffffffffu, mx0, 2));
        mn1 = fminf(mn1, __shfl_xor_sync(0xffffffffu, mn1, 1));
        mn1 = fminf(mn1, __shfl_xor_sync(0xffffffffu, mn1, 2));
        mx1 = fmaxf(mx1, __shfl_xor_sync(0xffffffffu, mx1, 1));
        mx1 = fmaxf(mx1, __shfl_xor_sync(0xffffffffu, mx1, 2));
        if ((lane & 3) == 0) {
            int r0 = jw * 32 + m * 16 + (lane >> 2);
            atomicMin(&rmn[r0], fkey(mn0));
            atomicMax(&rmx[r0], fkey(mx0));
            atomicMin(&rmn[r0 + 8], fkey(mn1));
            atomicMax(&rmx[r0 + 8], fkey(mx1));
        }
    }
#pragma unroll
    for (int m = 0; m < 2; ++m) {
        int r0 = jw * 32 + m * 16 + (lane >> 2);
#pragma unroll
        for (int nf = 0; nf < 7; ++nf) {
            int coln = cb + cw * 56 + nf * 8 + (lane & 3) * 2;
            *(float2*)&g_y[(size_t)(jb * 128 + r0) * MDIM + coln] =
                make_float2(acc[m][nf][0], acc[m][nf][1]);
            *(float2*)&g_y[(size_t)(jb * 128 + r0 + 8) * MDIM + coln] =
                make_float2(acc[m][nf][2], acc[m][nf][3]);
        }
    }
    __syncthreads();
    if (tid < 128) {
        atomicMin(&g_yminK[jb * 128 + tid], rmn[tid]);
        atomicMax(&g_ymaxK[jb * 128 + tid], rmx[tid]);
    }
    if (jb == 0) atomicAdd(&g_csum[tid], (unsigned long long)(long long)sc[tid]);
}

// -------- pass 2: mn, s[j] (exact fp32 from u), dmin/scale/inv --------
__global__ void k_prepS(const float* __restrict__ u, const float* __restrict__ cl) {
    __shared__ float wred[8];
    int j = blockIdx.x, c = threadIdx.x;
    int lane = c & 31, warp = c >> 5;
    float mnc = (float)(((double)g_csum[c] * (1.0 / 65536.0)) / (double)MDIM);
    if (c == j) g_mn[j] = mnc;
    float p = u[c * 256 + j] * mnc;
#pragma unroll
    for (int off = 16; off > 0; off >>= 1) p += __shfl_down_sync(0xffffffffu, p, off);
    if (lane == 0) wred[warp] = p;
    __syncthreads();
    if (c == 0) {
        float s = 0.f;
#pragma unroll
        for (int i = 0; i < 8; ++i) s += wred[i];
        g_s[j] = s;
        float ymin = kinv(g_yminK[j]) - s;
        float ymax = kinv(g_ymaxK[j]) - s;
        float cc = cl[j];
        float dmin = fminf(fmaxf(ymin, -cc), cc);
        float dmax = fminf(fmaxf(ymax, -cc), cc);
        float rng = dmax - dmin;
        float scale = 255.f / ((rng == 0.f) ? 1.f : rng);
        g_dmin[j]  = dmin;
        g_scale[j] = scale;
        g_inv[j]   = 1.f / scale;
    }
}

// -------- pass 3: quantize, fully-coalesced: block = 7168-elem span in one j row --------
__global__ __launch_bounds__(256) void k_quant() {
    int j   = blockIdx.x / 14;
    int seg = blockIdx.x - j * 14;
    int t   = threadIdx.x;
    float sc = g_scale[j];
    float bias = -(g_s[j] + g_dmin[j]) * sc;
    const float4* yb = (const float4*)(g_y + (size_t)j * MDIM + seg * 7168);
    float4 ya[7];
#pragma unroll
    for (int q = 0; q < 7; ++q) ya[q] = __ldcs(yb + q * 256 + t);
    unsigned ob[7];
    int ks = 0;
#pragma unroll
    for (int q = 0; q < 7; ++q) {
        int k0 = (int)fminf(fmaxf(rintf(fmaf(ya[q].x, sc, bias)), 0.f), 255.f);
        int k1 = (int)fminf(fmaxf(rintf(fmaf(ya[q].y, sc, bias)), 0.f), 255.f);
        int k2 = (int)fminf(fmaxf(rintf(fmaf(ya[q].z, sc, bias)), 0.f), 255.f);
        int k3 = (int)fminf(fmaxf(rintf(fmaf(ya[q].w, sc, bias)), 0.f), 255.f);
        ob[q] = (unsigned)k0 | ((unsigned)k1 << 8) | ((unsigned)k2 << 16) | ((unsigned)k3 << 24);
        ks += k0 + k1 + k2 + k3;
    }
    unsigned* kb = (unsigned*)(g_k + (size_t)j * MDIM + seg * 7168);
#pragma unroll
    for (int q = 0; q < 7; ++q) kb[q * 256 + t] = ob[q];
    ks = __reduce_add_sync(0xffffffffu, ks);
    if ((t & 31) == 0) atomicAdd(&g_ksum[j], ks);
}

// -------- pass 4: u' = fp16(u*inv), beta — warp-shuffle reduction --------
__global__ void k_prep2(const float* __restrict__ u) {
    __shared__ float w1[8], w2[8];
    int i = blockIdx.x, j = threadIdx.x;
    int lane = j & 31, warp = j >> 5;
    float v = u[i * 256 + j] * g_inv[j];
    __half hv = __float2half(v);
    g_upf16[i * 256 + j] = hv;
    float vq = __half2float(hv);
    float meank = (float)g_ksum[j] / (float)MDIM;
    float r1 = vq * meank;
    float r2 = vq;
#pragma unroll
    for (int off = 16; off > 0; off >>= 1) {
        r1 += __shfl_down_sync(0xffffffffu, r1, off);
        r2 += __shfl_down_sync(0xffffffffu, r2, off);
    }
    if (lane == 0) { w1[warp] = r1; w2[warp] = r2; }
    __syncthreads();
    if (j == 0) {
        float s1 = 0.f, s2 = 0.f;
#pragma unroll
        for (int q = 0; q < 8; ++q) { s1 += w1[q]; s2 += w2[q]; }
        g_beta[i] = g_mn[i] - s1 - 1024.f * s2;
    }
}

// ==================== GEMM2: out = u' @ (1024+k) + beta' (fp16, N=112 px, 2 CTA/SM) ====================
// buffer: A 10240 | B 8064 = 18304
#define G2_BUF 18304
__global__ __launch_bounds__(256, 2) void k_gemm2(float* __restrict__ out) {
    extern __shared__ __align__(16) char smem[];
    float* sbeta = (float*)smem;
    char*  bufs  = smem + 1024;

    const int tid = threadIdx.x, warp = tid >> 5, lane = tid & 31;
    const int jw = warp & 3, cw = warp >> 2;
    const int jb = blockIdx.x;
    const int cb = blockIdx.y * 112;
    const int c0 = warp * 4, g = lane;
    const bool act = g < 28;

    if (tid < 128) sbeta[tid] = g_beta[jb * 128 + tid];
    __syncthreads();

    const unsigned char* kt = g_k + (size_t)c0 * MDIM + cb + (act ? g : 0) * 4;

    const uint32_t bufs0 = (uint32_t)__cvta_generic_to_shared(bufs);
    const uint32_t aoff = (uint32_t)((jw * 32 + (lane & 7) + ((lane >> 3) & 1) * 8) * 80
                                     + ((lane >> 4) & 1) * 16);

    float acc[2][7][4];
#pragma unroll
    for (int m = 0; m < 2; ++m)
#pragma unroll
        for (int nf = 0; nf < 7; ++nf)
#pragma unroll
            for (int q = 0; q < 4; ++q) acc[m][nf][q] = 0.f;

    unsigned kr[4] = {0, 0, 0, 0};

    auto A_issue = [&](int c4, int buf) {
        const int kc = c4 * 32;
        char* base = bufs + buf * G2_BUF;
#pragma unroll
        for (int i = 0; i < 2; ++i) {
            int idx = tid + i * 256;
            int row = idx >> 2, seg = idx & 3;
            const __half* src = g_upf16 + (jb * 128 + row) * 256 + kc + seg * 8;
            uint32_t dst = (uint32_t)__cvta_generic_to_shared(base + row * 80 + seg * 16);
            cp16(dst, src);
        }
        asm volatile("cp.async.commit_group;" ::: "memory");
    };
    auto K_load = [&](int c4) {
        if (act) {
#pragma unroll
            for (int cc = 0; cc < 4; ++cc)
                kr[cc] = *(const unsigned*)(kt + (size_t)(c4 * 32 + cc) * MDIM);
        }
    };
    // fp16(1024 + k) == 0x6400 | k  (exact for k in [0,255]) — pure ALU conversion
    auto B_sts = [&](int buf) {
        if (!act) return;
        unsigned* Bw = (unsigned*)(bufs + buf * G2_BUF + 10240);
        const int w0 = c0 >> 1;
        const int xo = g & 15;
#pragma unroll
        for (int cc2 = 0; cc2 < 2; ++cc2) {
            unsigned a = kr[cc2 * 2], b = kr[cc2 * 2 + 1];
#pragma unroll
            for (int q = 0; q < 4; ++q) {
                unsigned t = __byte_perm(a, b, 0x0400 + 0x0101 * q);
                int r = g * 4 + q;
                Bw[r * 18 + ((w0 + cc2) ^ xo)] = (t & 0x00FF00FFu) | 0x64006400u;
            }
        }
    };

    A_issue(0, 0);
    K_load(0);
    B_sts(0);

#pragma unroll 2
    for (int c4 = 0; c4 < 8; ++c4) {
        const int buf = c4 & 1;
        asm volatile("cp.async.wait_group 0;" ::: "memory");
        __syncthreads();
        if (c4 < 7) {
            A_issue(c4 + 1, buf ^ 1);
            K_load(c4 + 1);
        }
        {
            const uint32_t Ab = bufs0 + buf * G2_BUF + aoff;
            const unsigned* Bw = (const unsigned*)(bufs + buf * G2_BUF + 10240);
#pragma unroll
            for (int ks = 0; ks < 2; ++ks) {
                unsigned af[2][4];
#pragma unroll
                for (int m = 0; m < 2; ++m)
                    ldm4(af[m], Ab + m * 1280 + ks * 32);
#pragma unroll
                for (int nf = 0; nf < 7; ++nf) {
                    int coln = cw * 56 + nf * 8 + (lane >> 2);
                    int wc   = ks * 8 + (lane & 3);
                    int xo   = (coln >> 2) & 15;
                    int rowb = coln * 18;
                    unsigned b[2];
                    b[0] = Bw[rowb + (wc ^ xo)];
                    b[1] = Bw[rowb + ((wc + 4) ^ xo)];
#pragma unroll
                    for (int m = 0; m < 2; ++m)
                        mma_f16(acc[m][nf], af[m], b);
                }
            }
        }
        if (c4 < 7) B_sts(buf ^ 1);
    }

    // epilogue: add beta', store NCHW
#pragma unroll
    for (int m = 0; m < 2; ++m) {
        int r0 = jw * 32 + m * 16 + (lane >> 2);
        int row0 = jb * 128 + r0;
        float b0 = sbeta[r0], b1 = sbeta[r0 + 8];
#pragma unroll
        for (int nf = 0; nf < 7; ++nf) {
            int col = cb + cw * 56 + nf * 8 + (lane & 3) * 2;
            int n = col / HW, hw2 = col - n * HW;
            *(float2*)&out[(size_t)n * CHW + (size_t)row0 * HW + hw2] =
                make_float2(acc[m][nf][0] + b0, acc[m][nf][1] + b0);
            *(float2*)&out[(size_t)n * CHW + (size_t)(row0 + 8) * HW + hw2] =
                make_float2(acc[m][nf][2] + b1, acc[m][nf][3] + b1);
        }
    }
}

extern "C" void kernel_launch(void* const* d_in, const int* in_sizes, int n_in,
                              void* d_out, int out_size) {
    const float* x  = (const float*)d_in[0];
    const float* u  = (const float*)d_in[1];
    const float* cl = (const float*)d_in[2];
    float* out = (float*)d_out;

    cudaFuncSetAttribute(k_gemm1, cudaFuncAttributeMaxDynamicSharedMemorySize, 2048 + 2 * G1_BUF);
    cudaFuncSetAttribute(k_gemm2, cudaFuncAttributeMaxDynamicSharedMemorySize, 1024 + 2 * G2_BUF);

    k_prep0<<<256, 256>>>(u);
    k_gemm1<<<dim3(2, 896), 256, 2048 + 2 * G1_BUF>>>(x);
    k_prepS<<<256, 256>>>(u, cl);
    k_quant<<<3584, 256>>>();
    k_prep2<<<256, 256>>>(u);
    k_gemm2<<<dim3(2, 896), 256, 1024 + 2 * G2_BUF>>>(out);
}